// round 5
// baseline (speedup 1.0000x reference)
#include <cuda_runtime.h>
#include <math.h>

// Fixed problem shapes
#define FCN   16
#define WT    593          // (FC+2)*FC + FC + FC*FC + FC + FC + 1
#define H_    152
#define W_    272
#define HW_   41344
#define B_    4
#define M_    32
#define BM_   128
#define EPS_  1.0e-4f

#define THREADS 128
#define PXPT    4                       // pixels per thread per iteration
#define PIXB    2048                    // pixels per block
#define NTILES  ((HW_ + PIXB - 1) / PIXB)   // 21

// Scratch accumulators (allocations forbidden) — zeroed each launch.
__device__ double g_neg_acc;
__device__ double g_pos_acc;

__global__ void zero_acc_kernel() {
    g_neg_acc = 0.0;
    g_pos_acc = 0.0;
}

// ---- packed f32x2 FMA on float2 (pair movs coalesce in ptxas) ----
__device__ __forceinline__ void fma2(float2& d, float2 a, float2 b, float2 c) {
    asm("{\n\t"
        ".reg .b64 ra, rb, rc;\n\t"
        "mov.b64 ra, {%2, %3};\n\t"
        "mov.b64 rb, {%4, %5};\n\t"
        "mov.b64 rc, {%6, %7};\n\t"
        "fma.rn.f32x2 rc, ra, rb, rc;\n\t"
        "mov.b64 {%0, %1}, rc;\n\t"
        "}"
        : "=f"(d.x), "=f"(d.y)
        : "f"(a.x), "f"(a.y), "f"(b.x), "f"(b.y), "f"(c.x), "f"(c.y));
}
__device__ __forceinline__ float2 relu2(float2 a) {   // FMNMX x2: alu pipe
    return make_float2(fmaxf(a.x, 0.0f), fmaxf(a.y, 0.0f));
}
#define F2(a, b) make_float2((a), (b))

// Shared layout (duplicated: float slot pair [2i,2i+1] holds [w_i, w_i]):
//   [0, 288)    w1[o*18 + c]
//   [288, 304)  b1[o]
//   [304, 560)  w2[o*16 + c]
//   [560, 576)  b2[o]
//   [576, 592)  w3[c]
//   [592]       b3
__global__ __launch_bounds__(THREADS, 4)
void sch_loss_main(const float* __restrict__ sch_feat,
                   const float* __restrict__ conv_weight,
                   const float* __restrict__ mask,
                   const int*   __restrict__ pre_ind,
                   const float* __restrict__ target,
                   const int*   __restrict__ ind)
{
    __shared__ __align__(16) float sdup[2 * WT];
    __shared__ float sred[THREADS / 32];

    const int bm  = blockIdx.y;        // b*32 + m
    const int b   = bm >> 5;
    const int tid = threadIdx.x;
    const int pi  = pre_ind[bm];

    // Gather 593-float weight vector (strided over conv_weight (B, WT, H*W)), duplicated.
    for (int c = tid; c < WT; c += THREADS) {
        const float v = conv_weight[((long long)b * WT + c) * HW_ + pi];
        sdup[2 * c]     = v;
        sdup[2 * c + 1] = v;
    }
    __syncthreads();

    // dup-pair loader: float4 at &sdup[2i] = (w_i, w_i, w_{i+1}, w_{i+1}), i even
    const float4* __restrict__ swq = (const float4*)sdup;   // swq[i/... index by (i>>1)? no:
    // float4 index j covers float slots [4j,4j+4) = dup slots {2j, 2j+1}: weights (w_{2j}? )
    // Careful: float4 j = floats sdup[4j..4j+3] = weights w_{2j}, w_{2j+1} duplicated.
    // For weight index i (even), float4 index = i/2.

    const float* __restrict__ sf = sch_feat + (long long)b * FCN * HW_;
    const float* __restrict__ tg = target   + (long long)bm * HW_;
    const int   posind = ind[bm];
    const float mval   = mask[bm];

    const float x0 = (float)(pi % W_);
    const float y0 = (float)pi / (float)W_;     // float division, matching reference
    const float inv128 = 1.0f / 128.0f;

    const int base  = blockIdx.x * PIXB;
    const int limit = (base + PIXB < HW_) ? (base + PIXB) : HW_;  // multiple of 4

    float negAcc = 0.0f;

    for (int p = base + PXPT * tid; p < limit; p += PXPT * THREADS) {
        // relative coords: 272 % 4 == 0 so no row wrap inside the 4-pixel group
        const int   px = p % W_;
        const float yr = ((float)(p / W_) - y0) * inv128;
        const float xr0 = ((float)px - x0) * inv128;
        const float2 xrA = F2(xr0, xr0 + inv128);
        const float2 xrB = F2(xr0 + 2.0f * inv128, xr0 + 3.0f * inv128);
        const float2 yrP = F2(yr, yr);

        // prefetch target early (overlaps with MLP)
        const float4 t4 = *(const float4*)(tg + p);

        // ---- layer 1 (18 -> 16) ----
        float2 hA[FCN], hB[FCN];
        #pragma unroll
        for (int o = 0; o < FCN; o += 2) {
            const float4 bp = swq[(288 + o) >> 1];
            hA[o]     = F2(bp.x, bp.y); hB[o]     = F2(bp.x, bp.y);
            hA[o + 1] = F2(bp.z, bp.w); hB[o + 1] = F2(bp.z, bp.w);
        }

        // 4 batches of 4 feature channels; batched LDG.128 per channel
        #pragma unroll
        for (int batch = 0; batch < 4; ++batch) {
            const int c0 = batch * 4;
            float4 v0 = *(const float4*)(sf + (long long)(c0    ) * HW_ + p);
            float4 v1 = *(const float4*)(sf + (long long)(c0 + 1) * HW_ + p);
            float4 v2 = *(const float4*)(sf + (long long)(c0 + 2) * HW_ + p);
            float4 v3 = *(const float4*)(sf + (long long)(c0 + 3) * HW_ + p);
            #pragma unroll
            for (int o = 0; o < FCN; ++o) {
                const int wb = o * 18 + c0;              // even -> aligned float4 pairs
                const float4 w01 = swq[wb >> 1];
                const float4 w23 = swq[(wb >> 1) + 1];
                // adjacent instructions share the weight pair (reuse cache)
                fma2(hA[o], F2(v0.x, v0.y), F2(w01.x, w01.y), hA[o]);
                fma2(hB[o], F2(v0.z, v0.w), F2(w01.x, w01.y), hB[o]);
                fma2(hA[o], F2(v1.x, v1.y), F2(w01.z, w01.w), hA[o]);
                fma2(hB[o], F2(v1.z, v1.w), F2(w01.z, w01.w), hB[o]);
                fma2(hA[o], F2(v2.x, v2.y), F2(w23.x, w23.y), hA[o]);
                fma2(hB[o], F2(v2.z, v2.w), F2(w23.x, w23.y), hB[o]);
                fma2(hA[o], F2(v3.x, v3.y), F2(w23.z, w23.w), hA[o]);
                fma2(hB[o], F2(v3.z, v3.w), F2(w23.z, w23.w), hB[o]);
            }
        }

        // coordinate channels (c = 16,17 -> one aligned float4) + relu
        #pragma unroll
        for (int o = 0; o < FCN; ++o) {
            const float4 w = swq[(o * 18 + 16) >> 1];   // (wx,wx,wy,wy)
            fma2(hA[o], xrA, F2(w.x, w.y), hA[o]);
            fma2(hB[o], xrB, F2(w.x, w.y), hB[o]);
            fma2(hA[o], yrP, F2(w.z, w.w), hA[o]);
            fma2(hB[o], yrP, F2(w.z, w.w), hB[o]);
            hA[o] = relu2(hA[o]);
            hB[o] = relu2(hB[o]);
        }

        // ---- layer 2 (16 -> 16) in o-pairs, fused with layer 3 (16 -> 1) ----
        float2 zA = F2(sdup[2 * 592], sdup[2 * 592]);
        float2 zB = zA;
        #pragma unroll
        for (int o = 0; o < FCN; o += 2) {
            const float4 bp = swq[(560 + o) >> 1];      // (b2o,b2o,b2o1,b2o1)
            float2 a0A = F2(bp.x, bp.y), a0B = a0A;
            float2 a1A = F2(bp.z, bp.w), a1B = a1A;
            const int wb0 = 304 + o * 16;
            const int wb1 = wb0 + 16;
            #pragma unroll
            for (int c = 0; c < FCN; c += 2) {
                const float4 w0 = swq[(wb0 + c) >> 1];
                const float4 w1 = swq[(wb1 + c) >> 1];
                fma2(a0A, hA[c],     F2(w0.x, w0.y), a0A);
                fma2(a0B, hB[c],     F2(w0.x, w0.y), a0B);
                fma2(a0A, hA[c + 1], F2(w0.z, w0.w), a0A);
                fma2(a0B, hB[c + 1], F2(w0.z, w0.w), a0B);
                fma2(a1A, hA[c],     F2(w1.x, w1.y), a1A);
                fma2(a1B, hB[c],     F2(w1.x, w1.y), a1B);
                fma2(a1A, hA[c + 1], F2(w1.z, w1.w), a1A);
                fma2(a1B, hB[c + 1], F2(w1.z, w1.w), a1B);
            }
            const float2 g0A = relu2(a0A), g0B = relu2(a0B);
            const float2 g1A = relu2(a1A), g1B = relu2(a1B);
            const float4 w3 = swq[(576 + o) >> 1];      // (w3o,w3o,w3o1,w3o1)
            fma2(zA, g0A, F2(w3.x, w3.y), zA);
            fma2(zB, g0B, F2(w3.x, w3.y), zB);
            fma2(zA, g1A, F2(w3.z, w3.w), zA);
            fma2(zB, g1B, F2(w3.z, w3.w), zB);
        }

        // ---- epilogue: sigmoid + clip + focal terms ----
        const float z[4]  = {zA.x, zA.y, zB.x, zB.y};
        const float tt[4] = {t4.x, t4.y, t4.z, t4.w};

        #pragma unroll
        for (int i = 0; i < 4; ++i) {
            float hm = 1.0f / (1.0f + __expf(-z[i]));
            hm = fminf(fmaxf(hm, EPS_), 1.0f - EPS_);
            float q = 1.0f - tt[i];
            q = q * q; q = q * q;                       // (1-t)^4
            negAcc += __logf(1.0f - hm) * hm * hm * q;
            if (p + i == posind) {
                const float om = 1.0f - hm;
                atomicAdd(&g_pos_acc, (double)(__logf(hm) * om * om * mval));
            }
        }
    }

    // ---- block reduction, one double atomic per block ----
    #pragma unroll
    for (int off = 16; off > 0; off >>= 1)
        negAcc += __shfl_down_sync(0xFFFFFFFFu, negAcc, off);
    if ((tid & 31) == 0) sred[tid >> 5] = negAcc;
    __syncthreads();
    if (tid < 32) {
        float v = (tid < THREADS / 32) ? sred[tid] : 0.0f;
        #pragma unroll
        for (int off = 2; off > 0; off >>= 1)
            v += __shfl_down_sync(0xFFFFFFFFu, v, off);
        if (tid == 0) atomicAdd(&g_neg_acc, (double)v);
    }
}

__global__ void finalize_kernel(const float* __restrict__ mask, float* __restrict__ out)
{
    if (threadIdx.x == 0) {
        float np = 0.0f;
        for (int i = 0; i < BM_; ++i) np += mask[i];
        const double neg = g_neg_acc;
        const double pos = g_pos_acc;
        double loss;
        if (np == 0.0f) loss = -neg;
        else            loss = -(pos + neg) / (double)fmaxf(np, 1.0f);
        out[0] = (float)loss;
    }
}

extern "C" void kernel_launch(void* const* d_in, const int* in_sizes, int n_in,
                              void* d_out, int out_size)
{
    const float* sch_feat    = (const float*)d_in[0];
    const float* conv_weight = (const float*)d_in[1];
    const float* mask        = (const float*)d_in[2];
    const int*   pre_ind     = (const int*)  d_in[3];
    const float* target      = (const float*)d_in[4];
    const int*   ind         = (const int*)  d_in[5];
    float* out = (float*)d_out;

    zero_acc_kernel<<<1, 1>>>();

    dim3 grid(NTILES, BM_);
    sch_loss_main<<<grid, THREADS>>>(sch_feat, conv_weight, mask, pre_ind, target, ind);

    finalize_kernel<<<1, 32>>>(mask, out);
}

// round 6
// speedup vs baseline: 1.3138x; 1.3138x over previous
#include <cuda_runtime.h>
#include <cuda_fp16.h>
#include <math.h>

// Fixed problem shapes
#define FCN   16
#define WT    593          // (FC+2)*FC + FC + FC*FC + FC + FC + 1
#define H_    152
#define W_    272
#define HW_   41344
#define B_    4
#define M_    32
#define BM_   128
#define EPS_  1.0e-4f

#define THREADS 128
#define PXPT    4                       // pixels per thread per iteration
#define PIXB    2048                    // pixels per block
#define NTILES  ((HW_ + PIXB - 1) / PIXB)   // 21

// Scratch accumulators (allocations forbidden) — zeroed each launch.
__device__ double g_neg_acc;
__device__ double g_pos_acc;

__global__ void zero_acc_kernel() {
    g_neg_acc = 0.0;
    g_pos_acc = 0.0;
}

// load an 8-byte-aligned pair of dup half2 weights (i must be even)
__device__ __forceinline__ void ldpair(const __half2* __restrict__ swh, int i,
                                       __half2& w0, __half2& w1) {
    const uint2 v = *(const uint2*)&swh[i];
    w0 = *reinterpret_cast<const __half2*>(&v.x);
    w1 = *reinterpret_cast<const __half2*>(&v.y);
}

// Shared layout (half2 dup: swh[i] = (w_i, w_i)):
//   [0, 288)    w1[o*18 + c]
//   [288, 304)  b1[o]
//   [304, 560)  w2[o*16 + c]
//   [560, 576)  b2[o]
//   [576, 592)  w3[c]
//   [592]       b3
__global__ __launch_bounds__(THREADS, 4)
void sch_loss_main(const float* __restrict__ sch_feat,
                   const float* __restrict__ conv_weight,
                   const float* __restrict__ mask,
                   const int*   __restrict__ pre_ind,
                   const float* __restrict__ target,
                   const int*   __restrict__ ind)
{
    __shared__ __align__(16) __half2 swh[WT + 1];
    __shared__ float sred[THREADS / 32];

    const int bm  = blockIdx.y;        // b*32 + m
    const int b   = bm >> 5;
    const int tid = threadIdx.x;
    const int pi  = pre_ind[bm];

    // Gather 593-float weight vector (strided), convert to duplicated half2.
    for (int c = tid; c < WT; c += THREADS) {
        const float v = conv_weight[((long long)b * WT + c) * HW_ + pi];
        swh[c] = __floats2half2_rn(v, v);
    }
    __syncthreads();

    const float* __restrict__ sf = sch_feat + (long long)b * FCN * HW_;
    const float* __restrict__ tg = target   + (long long)bm * HW_;
    const int   posind = ind[bm];
    const float mval   = mask[bm];

    const float x0 = (float)(pi % W_);
    const float y0 = (float)pi / (float)W_;     // float division, matching reference
    const float inv128 = 1.0f / 128.0f;

    const int base  = blockIdx.x * PIXB;
    const int limit = (base + PIXB < HW_) ? (base + PIXB) : HW_;  // multiple of 4

    float negAcc = 0.0f;

    const __half2 h2zero = __floats2half2_rn(0.0f, 0.0f);

    for (int p = base + PXPT * tid; p < limit; p += PXPT * THREADS) {
        // relative coords: 272 % 4 == 0 so no row wrap inside the 4-pixel group
        const int   px = p % W_;
        const float yr = ((float)(p / W_) - y0) * inv128;
        const float xr0 = ((float)px - x0) * inv128;
        const __half2 xrA = __floats2half2_rn(xr0, xr0 + inv128);
        const __half2 xrB = __floats2half2_rn(xr0 + 2.0f * inv128, xr0 + 3.0f * inv128);
        const __half2 yrP = __floats2half2_rn(yr, yr);

        // prefetch target (overlaps MLP)
        const float4 t4 = *(const float4*)(tg + p);

        // ---- layer 1 (18 -> 16): batched feature loads, per-o rows ----
        __half2 hA[FCN], hB[FCN];

        // init accumulators with bias (paired 8B LDS at even o)
        #pragma unroll
        for (int o = 0; o < FCN; o += 2) {
            __half2 b0, b1x;
            ldpair(swh, 288 + o, b0, b1x);
            hA[o] = b0;  hB[o] = b0;
            hA[o + 1] = b1x; hB[o + 1] = b1x;
        }

        // two half-batches of 8 channels: batched LDG.128s -> fp16, then accumulate
        #pragma unroll
        for (int half = 0; half < 2; ++half) {
            const int c0 = half * 8;
            __half2 fA[8], fB[8];
            #pragma unroll
            for (int c = 0; c < 8; ++c) {
                const float4 v = *(const float4*)(sf + (long long)(c0 + c) * HW_ + p);
                fA[c] = __floats2half2_rn(v.x, v.y);
                fB[c] = __floats2half2_rn(v.z, v.w);
            }
            #pragma unroll
            for (int o = 0; o < FCN; ++o) {
                const int wb = o * 18 + c0;          // even -> aligned pairs
                __half2 aA = hA[o];
                __half2 aB = hB[o];
                #pragma unroll
                for (int c = 0; c < 8; c += 2) {
                    __half2 w0, w1;
                    ldpair(swh, wb + c, w0, w1);
                    aA = __hfma2(w0, fA[c], aA);
                    aB = __hfma2(w0, fB[c], aB);
                    aA = __hfma2(w1, fA[c + 1], aA);
                    aB = __hfma2(w1, fB[c + 1], aB);
                }
                hA[o] = aA;
                hB[o] = aB;
            }
        }

        // coordinate channels (c = 16,17 -> aligned pair) + relu
        #pragma unroll
        for (int o = 0; o < FCN; ++o) {
            __half2 wx, wy;
            ldpair(swh, o * 18 + 16, wx, wy);
            __half2 aA = hA[o];
            __half2 aB = hB[o];
            aA = __hfma2(wx, xrA, aA); aA = __hfma2(wy, yrP, aA);
            aB = __hfma2(wx, xrB, aB); aB = __hfma2(wy, yrP, aB);
            hA[o] = __hmax2(aA, h2zero);
            hB[o] = __hmax2(aB, h2zero);
        }

        // ---- layer 2 (16 -> 16) fused with layer 3 (16 -> 1) ----
        __half2 zA = swh[592];
        __half2 zB = zA;
        #pragma unroll
        for (int o = 0; o < FCN; o += 2) {
            __half2 b20, b21;
            ldpair(swh, 560 + o, b20, b21);
            __half2 a0A = b20, a0B = b20;
            __half2 a1A = b21, a1B = b21;
            const int wb0 = 304 + o * 16;
            const int wb1 = wb0 + 16;
            #pragma unroll
            for (int c = 0; c < FCN; c += 2) {
                __half2 w00, w01, w10, w11;
                ldpair(swh, wb0 + c, w00, w01);
                ldpair(swh, wb1 + c, w10, w11);
                a0A = __hfma2(w00, hA[c],     a0A);
                a0B = __hfma2(w00, hB[c],     a0B);
                a0A = __hfma2(w01, hA[c + 1], a0A);
                a0B = __hfma2(w01, hB[c + 1], a0B);
                a1A = __hfma2(w10, hA[c],     a1A);
                a1B = __hfma2(w10, hB[c],     a1B);
                a1A = __hfma2(w11, hA[c + 1], a1A);
                a1B = __hfma2(w11, hB[c + 1], a1B);
            }
            const __half2 g0A = __hmax2(a0A, h2zero);
            const __half2 g0B = __hmax2(a0B, h2zero);
            const __half2 g1A = __hmax2(a1A, h2zero);
            const __half2 g1B = __hmax2(a1B, h2zero);
            __half2 w30, w31;
            ldpair(swh, 576 + o, w30, w31);
            zA = __hfma2(w30, g0A, zA);
            zB = __hfma2(w30, g0B, zB);
            zA = __hfma2(w31, g1A, zA);
            zB = __hfma2(w31, g1B, zB);
        }

        // ---- epilogue (fp32): sigmoid + clip + focal terms ----
        const float2 zAf = __half22float2(zA);
        const float2 zBf = __half22float2(zB);
        const float z[4]  = {zAf.x, zAf.y, zBf.x, zBf.y};
        const float tt[4] = {t4.x, t4.y, t4.z, t4.w};

        #pragma unroll
        for (int i = 0; i < 4; ++i) {
            float hm = 1.0f / (1.0f + __expf(-z[i]));
            hm = fminf(fmaxf(hm, EPS_), 1.0f - EPS_);
            float q = 1.0f - tt[i];
            q = q * q; q = q * q;                       // (1-t)^4
            negAcc += __logf(1.0f - hm) * hm * hm * q;
            if (p + i == posind) {
                const float om = 1.0f - hm;
                atomicAdd(&g_pos_acc, (double)(__logf(hm) * om * om * mval));
            }
        }
    }

    // ---- block reduction, one double atomic per block ----
    #pragma unroll
    for (int off = 16; off > 0; off >>= 1)
        negAcc += __shfl_down_sync(0xFFFFFFFFu, negAcc, off);
    if ((tid & 31) == 0) sred[tid >> 5] = negAcc;
    __syncthreads();
    if (tid < 32) {
        float v = (tid < THREADS / 32) ? sred[tid] : 0.0f;
        #pragma unroll
        for (int off = 2; off > 0; off >>= 1)
            v += __shfl_down_sync(0xFFFFFFFFu, v, off);
        if (tid == 0) atomicAdd(&g_neg_acc, (double)v);
    }
}

__global__ void finalize_kernel(const float* __restrict__ mask, float* __restrict__ out)
{
    if (threadIdx.x == 0) {
        float np = 0.0f;
        for (int i = 0; i < BM_; ++i) np += mask[i];
        const double neg = g_neg_acc;
        const double pos = g_pos_acc;
        double loss;
        if (np == 0.0f) loss = -neg;
        else            loss = -(pos + neg) / (double)fmaxf(np, 1.0f);
        out[0] = (float)loss;
    }
}

extern "C" void kernel_launch(void* const* d_in, const int* in_sizes, int n_in,
                              void* d_out, int out_size)
{
    const float* sch_feat    = (const float*)d_in[0];
    const float* conv_weight = (const float*)d_in[1];
    const float* mask        = (const float*)d_in[2];
    const int*   pre_ind     = (const int*)  d_in[3];
    const float* target      = (const float*)d_in[4];
    const int*   ind         = (const int*)  d_in[5];
    float* out = (float*)d_out;

    zero_acc_kernel<<<1, 1>>>();

    dim3 grid(NTILES, BM_);
    sch_loss_main<<<grid, THREADS>>>(sch_feat, conv_weight, mask, pre_ind, target, ind);

    finalize_kernel<<<1, 32>>>(mask, out);
}